// round 5
// baseline (speedup 1.0000x reference)
#include <cuda_runtime.h>
#include <math.h>

#define Bb 8
#define Tt 1024
#define Cc 768
#define Hh 12
#define Dd 64
#define Ll 6
#define Vv 50257

// ---------------- scratch (no allocations allowed) ----------------
__device__ __align__(16) float g_x[Bb * Tt * Cc];        // residual stream
__device__ __align__(16) float g_h[Bb * Tt * Cc];        // ln output
__device__ __align__(16) float g_y[Bb * Tt * Cc];        // attn output
__device__ __align__(16) float g_qkv[Bb * Tt * 3 * Cc];  // qkv
__device__ __align__(16) float g_m[Bb * Tt * 4 * Cc];    // mlp hidden
__device__ __align__(16) float g_xl[Bb * Cc];            // lnf(last pos)

// ---------------- embedding ----------------
__global__ void embed_kernel(const int* __restrict__ idx,
                             const float* __restrict__ wte,
                             const float* __restrict__ wpe) {
    int i = blockIdx.x * blockDim.x + threadIdx.x;
    if (i >= Bb * Tt * Cc) return;
    int c = i % Cc;
    int bt = i / Cc;
    int t = bt % Tt;
    g_x[i] = wte[(long)idx[bt] * Cc + c] + wpe[t * Cc + c];
}

// ---------------- layernorm (one block per row, C=768) ----------------
__global__ __launch_bounds__(256) void ln_kernel(const float* __restrict__ in,
                                                 float* __restrict__ out,
                                                 const float* __restrict__ w,
                                                 const float* __restrict__ b,
                                                 long in_stride, long in_off) {
    int r = blockIdx.x;
    int tid = threadIdx.x;
    const float* xr = in + (long)r * in_stride + in_off;
    float v0 = xr[tid], v1 = xr[tid + 256], v2 = xr[tid + 512];
    __shared__ float red[256];
    red[tid] = v0 + v1 + v2;
    __syncthreads();
    for (int off = 128; off; off >>= 1) {
        if (tid < off) red[tid] += red[tid + off];
        __syncthreads();
    }
    float mean = red[0] * (1.0f / 768.0f);
    __syncthreads();
    float d0 = v0 - mean, d1 = v1 - mean, d2 = v2 - mean;
    red[tid] = d0 * d0 + d1 * d1 + d2 * d2;
    __syncthreads();
    for (int off = 128; off; off >>= 1) {
        if (tid < off) red[tid] += red[tid + off];
        __syncthreads();
    }
    float rstd = rsqrtf(red[0] * (1.0f / 768.0f) + 1e-5f);
    float* orow = out + (long)r * Cc;
    orow[tid]       = d0 * rstd * w[tid]       + b[tid];
    orow[tid + 256] = d1 * rstd * w[tid + 256] + b[tid + 256];
    orow[tid + 512] = d2 * rstd * w[tid + 512] + b[tid + 512];
}

// ---------------- SGEMM: out[m,n] = sum_k A[m,k]*W[n,k] + bias[n] (+res) (+gelu)
// BM=BN=128, BK=8, 256 threads, 8x8 per thread. M,N %128==0, K %8==0.
template <bool GELU, bool RESID>
__global__ __launch_bounds__(256) void sgemm_kernel(
    const float* __restrict__ A, const float* __restrict__ W,
    const float* __restrict__ bias, const float* __restrict__ res,
    float* __restrict__ out, int M, int N, int K) {
    __shared__ float As[8][128];
    __shared__ float Ws[8][128];
    int tid = threadIdx.x;
    int m0 = blockIdx.y * 128;
    int n0 = blockIdx.x * 128;
    int lr = tid >> 1;
    int lc = (tid & 1) * 4;
    int tx = tid & 15, ty = tid >> 4;
    float acc[8][8];
#pragma unroll
    for (int i = 0; i < 8; i++)
#pragma unroll
        for (int j = 0; j < 8; j++) acc[i][j] = 0.0f;

    const float* Ap = A + (long)(m0 + lr) * K + lc;
    const float* Wp = W + (long)(n0 + lr) * K + lc;
    for (int k0 = 0; k0 < K; k0 += 8) {
        float4 a4 = *(const float4*)(Ap + k0);
        float4 w4 = *(const float4*)(Wp + k0);
        __syncthreads();
        As[lc + 0][lr] = a4.x; As[lc + 1][lr] = a4.y;
        As[lc + 2][lr] = a4.z; As[lc + 3][lr] = a4.w;
        Ws[lc + 0][lr] = w4.x; Ws[lc + 1][lr] = w4.y;
        Ws[lc + 2][lr] = w4.z; Ws[lc + 3][lr] = w4.w;
        __syncthreads();
#pragma unroll
        for (int kk = 0; kk < 8; kk++) {
            float ar[8], br[8];
#pragma unroll
            for (int i = 0; i < 8; i++) ar[i] = As[kk][ty * 8 + i];
#pragma unroll
            for (int j = 0; j < 8; j++) br[j] = Ws[kk][tx * 8 + j];
#pragma unroll
            for (int i = 0; i < 8; i++)
#pragma unroll
                for (int j = 0; j < 8; j++) acc[i][j] += ar[i] * br[j];
        }
    }
#pragma unroll
    for (int i = 0; i < 8; i++) {
        int m = m0 + ty * 8 + i;
#pragma unroll
        for (int j = 0; j < 8; j++) {
            int n = n0 + tx * 8 + j;
            float v = acc[i][j] + bias[n];
            if (RESID) v += res[(long)m * N + n];
            if (GELU) v = 0.5f * v * (1.0f + erff(v * 0.70710678118654752f));
            out[(long)m * N + n] = v;
        }
    }
}

// ---------------- fused LIF attention ----------------
// 16 queries per block (16 warps / 512 threads), K/V tiles of 64 rows in smem.
// Pass 1: online softmax max/Z.  Pass 2: recompute s, LIF-gate, renormalize, PV.
__global__ __launch_bounds__(512) void attn_kernel(
    const float* __restrict__ qkv, float* __restrict__ y,
    const float* __restrict__ thr, const float* __restrict__ leak,
    const float* __restrict__ steep) {
    __shared__ float qs[16][64];
    __shared__ float Ks[64][65];
    __shared__ float Vs[64][65];
    __shared__ float modbuf[16][64];

    int b = blockIdx.z, hh = blockIdx.y;
    int q0 = blockIdx.x * 16;
    int tid = threadIdx.x;
    int w = tid >> 5, lane = tid & 31;

    float th = fabsf(thr[hh]) * 0.1f;
    float lk = 1.0f / (1.0f + __expf(-leak[hh]));
    float sp_in = steep[hh];
    float st = (sp_in > 20.0f) ? sp_in : log1pf(__expf(sp_in));

    // load Q tile (16 x 64)
    for (int i = 0; i < 2; i++) {
        int e = tid + i * 512;
        int r = e >> 6, c = e & 63;
        qs[r][c] = qkv[((long)(b * Tt + q0 + r)) * 2304 + hh * 64 + c];
    }
    int qpos = q0 + w;
    int ntiles = (q0 + 15) / 64 + 1;
    const float scale = 0.125f;
    const long kbase = (long)b * Tt * 2304 + 768 + hh * 64;

    // ---- pass 1: max & Z (online, per-lane then warp merge) ----
    float mval = -INFINITY, zval = 0.0f;
    for (int kt = 0; kt < ntiles; kt++) {
        __syncthreads();
        for (int i = 0; i < 8; i++) {
            int e = tid + i * 512;
            int r = e >> 6, c = e & 63;
            Ks[r][c] = qkv[kbase + (long)(kt * 64 + r) * 2304 + c];
        }
        __syncthreads();
#pragma unroll
        for (int jj = 0; jj < 2; jj++) {
            int j = jj * 32 + lane;
            int kpos = kt * 64 + j;
            if (kpos <= qpos) {
                float s = 0.0f;
#pragma unroll
                for (int d = 0; d < 64; d++) s += qs[w][d] * Ks[j][d];
                s *= scale;
                float nm = fmaxf(mval, s);
                zval = zval * __expf(mval - nm) + __expf(s - nm);
                mval = nm;
            }
        }
    }
#pragma unroll
    for (int off = 16; off >= 1; off >>= 1) {
        float m2 = __shfl_xor_sync(0xffffffffu, mval, off);
        float z2 = __shfl_xor_sync(0xffffffffu, zval, off);
        float nm = fmaxf(mval, m2);
        float e1 = (mval == -INFINITY) ? 0.0f : __expf(mval - nm);
        float e2 = (m2 == -INFINITY) ? 0.0f : __expf(m2 - nm);
        zval = zval * e1 + z2 * e2;
        mval = nm;
    }
    float inv_z = 1.0f / zval;

    // ---- pass 2: LIF modulate + PV ----
    float acc0 = 0.0f, acc1 = 0.0f, smod = 0.0f;
    int d0 = lane * 2, d1 = lane * 2 + 1;
    for (int kt = 0; kt < ntiles; kt++) {
        __syncthreads();
        for (int i = 0; i < 8; i++) {
            int e = tid + i * 512;
            int r = e >> 6, c = e & 63;
            long row = kbase + (long)(kt * 64 + r) * 2304 + c;
            Ks[r][c] = qkv[row];
            Vs[r][c] = qkv[row + 768];
        }
        __syncthreads();
#pragma unroll
        for (int jj = 0; jj < 2; jj++) {
            int j = jj * 32 + lane;
            int kpos = kt * 64 + j;
            float mod = 0.0f;
            if (kpos <= qpos) {
                float s = 0.0f;
#pragma unroll
                for (int d = 0; d < 64; d++) s += qs[w][d] * Ks[j][d];
                s *= scale;
                float p = __expf(s - mval) * inv_z;
                float fire = 1.0f / (1.0f + __expf(-st * (p - th)));
                float wg = fire + lk * (1.0f - fire);
                mod = p * wg;
            }
            modbuf[w][j] = mod;
            smod += mod;
        }
        __syncwarp();
#pragma unroll 8
        for (int j = 0; j < 64; j++) {
            float mv = modbuf[w][j];
            acc0 += mv * Vs[j][d0];
            acc1 += mv * Vs[j][d1];
        }
    }
#pragma unroll
    for (int off = 16; off >= 1; off >>= 1)
        smod += __shfl_xor_sync(0xffffffffu, smod, off);
    float inv_s = 1.0f / (smod + 1e-8f);
    long yo = ((long)(b * Tt + qpos)) * Cc + hh * 64;
    y[yo + d0] = acc0 * inv_s;
    y[yo + d1] = acc1 * inv_s;
}

// ---------------- tied lm head: out[r, n] = dot(xl[r,:], wte[n,:]) ----------------
__global__ __launch_bounds__(256) void lmhead_kernel(const float* __restrict__ wte,
                                                     float* __restrict__ out) {
    __shared__ float xs[Bb * Cc];
    int tid = threadIdx.x;
    for (int i = tid; i < Bb * Cc; i += 256) xs[i] = g_xl[i];
    __syncthreads();
    int warp = tid >> 5, lane = tid & 31;
    int n = blockIdx.x * 8 + warp;
    if (n >= Vv) return;
    float acc[Bb];
#pragma unroll
    for (int r = 0; r < Bb; r++) acc[r] = 0.0f;
    const float* wrow = wte + (long)n * Cc;
    for (int k = lane; k < Cc; k += 32) {
        float wv = wrow[k];
#pragma unroll
        for (int r = 0; r < Bb; r++) acc[r] += wv * xs[r * Cc + k];
    }
#pragma unroll
    for (int r = 0; r < Bb; r++)
#pragma unroll
        for (int off = 16; off >= 1; off >>= 1)
            acc[r] += __shfl_xor_sync(0xffffffffu, acc[r], off);
    if (lane == 0) {
#pragma unroll
        for (int r = 0; r < Bb; r++) out[(long)r * Vv + n] = acc[r];
    }
}

// ---------------- lnf into g_xl (8 last-position rows) ----------------
// reuse ln_kernel with stride Tt*Cc and offset (Tt-1)*Cc.

extern "C" void kernel_launch(void* const* d_in, const int* in_sizes, int n_in,
                              void* d_out, int out_size) {
    const int* idx      = (const int*)d_in[0];
    const float* wte    = (const float*)d_in[1];
    const float* wpe    = (const float*)d_in[2];
    const float* ln1_w  = (const float*)d_in[3];
    const float* ln1_b  = (const float*)d_in[4];
    const float* attn_w = (const float*)d_in[5];
    const float* attn_b = (const float*)d_in[6];
    const float* proj_w = (const float*)d_in[7];
    const float* proj_b = (const float*)d_in[8];
    const float* thr    = (const float*)d_in[9];
    const float* leak   = (const float*)d_in[10];
    const float* steep  = (const float*)d_in[11];
    const float* ln2_w  = (const float*)d_in[12];
    const float* ln2_b  = (const float*)d_in[13];
    const float* fc_w   = (const float*)d_in[14];
    const float* fc_b   = (const float*)d_in[15];
    const float* mproj_w= (const float*)d_in[16];
    const float* mproj_b= (const float*)d_in[17];
    const float* lnf_w  = (const float*)d_in[18];
    const float* lnf_b  = (const float*)d_in[19];
    float* out = (float*)d_out;

    float *px, *ph, *py, *pqkv, *pm, *pxl;
    cudaGetSymbolAddress((void**)&px, g_x);
    cudaGetSymbolAddress((void**)&ph, g_h);
    cudaGetSymbolAddress((void**)&py, g_y);
    cudaGetSymbolAddress((void**)&pqkv, g_qkv);
    cudaGetSymbolAddress((void**)&pm, g_m);
    cudaGetSymbolAddress((void**)&pxl, g_xl);

    const int Mrows = Bb * Tt;  // 8192

    embed_kernel<<<(Bb * Tt * Cc + 255) / 256, 256>>>(idx, wte, wpe);

    for (int l = 0; l < Ll; l++) {
        // ln1
        ln_kernel<<<Mrows, 256>>>(px, ph, ln1_w + l * Cc, ln1_b + l * Cc, Cc, 0);
        // qkv = h @ attn_w^T + attn_b
        {
            dim3 grid(3 * Cc / 128, Mrows / 128);
            sgemm_kernel<false, false><<<grid, 256>>>(
                ph, attn_w + (long)l * 3 * Cc * Cc, attn_b + l * 3 * Cc,
                nullptr, pqkv, Mrows, 3 * Cc, Cc);
        }
        // attention
        {
            dim3 grid(Tt / 16, Hh, Bb);
            attn_kernel<<<grid, 512>>>(pqkv, py, thr + l * Hh, leak + l * Hh,
                                       steep + l * Hh);
        }
        // x = x + y @ proj_w^T + proj_b
        {
            dim3 grid(Cc / 128, Mrows / 128);
            sgemm_kernel<false, true><<<grid, 256>>>(
                py, proj_w + (long)l * Cc * Cc, proj_b + l * Cc, px, px,
                Mrows, Cc, Cc);
        }
        // ln2
        ln_kernel<<<Mrows, 256>>>(px, ph, ln2_w + l * Cc, ln2_b + l * Cc, Cc, 0);
        // m = gelu(h @ fc_w^T + fc_b)
        {
            dim3 grid(4 * Cc / 128, Mrows / 128);
            sgemm_kernel<true, false><<<grid, 256>>>(
                ph, fc_w + (long)l * 4 * Cc * Cc, fc_b + l * 4 * Cc, nullptr,
                pm, Mrows, 4 * Cc, Cc);
        }
        // x = x + m @ mproj_w^T + mproj_b
        {
            dim3 grid(Cc / 128, Mrows / 128);
            sgemm_kernel<false, true><<<grid, 256>>>(
                pm, mproj_w + (long)l * Cc * 4 * Cc, mproj_b + l * Cc, px, px,
                Mrows, Cc, 4 * Cc);
        }
    }

    // lnf on last position of each batch row
    ln_kernel<<<Bb, 256>>>(px, pxl, lnf_w, lnf_b, (long)Tt * Cc,
                           (long)(Tt - 1) * Cc);
    // logits = xl @ wte^T
    lmhead_kernel<<<(Vv + 7) / 8, 256>>>(wte, out);
}

// round 6
// speedup vs baseline: 1.0007x; 1.0007x over previous
#include <cuda_runtime.h>
#include <math.h>

#define Bb 8
#define Tt 1024
#define Cc 768
#define Hh 12
#define Dd 64
#define Ll 6
#define Vv 50257

// ---------------- scratch (no allocations allowed) ----------------
__device__ __align__(16) float g_x[Bb * Tt * Cc];        // residual stream
__device__ __align__(16) float g_h[Bb * Tt * Cc];        // ln output
__device__ __align__(16) float g_y[Bb * Tt * Cc];        // attn output
__device__ __align__(16) float g_qkv[Bb * Tt * 3 * Cc];  // qkv
__device__ __align__(16) float g_m[Bb * Tt * 4 * Cc];    // mlp hidden
__device__ __align__(16) float g_xl[Bb * Cc];            // lnf(last pos)

// ---------------- embedding ----------------
__global__ void embed_kernel(const int* __restrict__ idx,
                             const float* __restrict__ wte,
                             const float* __restrict__ wpe) {
    int i = blockIdx.x * blockDim.x + threadIdx.x;
    if (i >= Bb * Tt * Cc) return;
    int c = i % Cc;
    int bt = i / Cc;
    int t = bt % Tt;
    g_x[i] = wte[(long)idx[bt] * Cc + c] + wpe[t * Cc + c];
}

// ---------------- layernorm (one block per row, C=768) ----------------
__global__ __launch_bounds__(256) void ln_kernel(const float* __restrict__ in,
                                                 float* __restrict__ out,
                                                 const float* __restrict__ w,
                                                 const float* __restrict__ b,
                                                 long in_stride, long in_off) {
    int r = blockIdx.x;
    int tid = threadIdx.x;
    const float* xr = in + (long)r * in_stride + in_off;
    float v0 = xr[tid], v1 = xr[tid + 256], v2 = xr[tid + 512];
    __shared__ float red[256];
    red[tid] = v0 + v1 + v2;
    __syncthreads();
    for (int off = 128; off; off >>= 1) {
        if (tid < off) red[tid] += red[tid + off];
        __syncthreads();
    }
    float mean = red[0] * (1.0f / 768.0f);
    __syncthreads();
    float d0 = v0 - mean, d1 = v1 - mean, d2 = v2 - mean;
    red[tid] = d0 * d0 + d1 * d1 + d2 * d2;
    __syncthreads();
    for (int off = 128; off; off >>= 1) {
        if (tid < off) red[tid] += red[tid + off];
        __syncthreads();
    }
    float rstd = rsqrtf(red[0] * (1.0f / 768.0f) + 1e-5f);
    float* orow = out + (long)r * Cc;
    orow[tid]       = d0 * rstd * w[tid]       + b[tid];
    orow[tid + 256] = d1 * rstd * w[tid + 256] + b[tid + 256];
    orow[tid + 512] = d2 * rstd * w[tid + 512] + b[tid + 512];
}

// ---------------- SGEMM: out[m,n] = sum_k A[m,k]*W[n,k] + bias[n] (+res) (+gelu)
// BM=BN=128, BK=8, 256 threads, 8x8 per thread. M,N %128==0, K %8==0.
template <bool GELU, bool RESID>
__global__ __launch_bounds__(256) void sgemm_kernel(
    const float* __restrict__ A, const float* __restrict__ W,
    const float* __restrict__ bias, const float* __restrict__ res,
    float* __restrict__ out, int M, int N, int K) {
    __shared__ float As[8][128];
    __shared__ float Ws[8][128];
    int tid = threadIdx.x;
    int m0 = blockIdx.y * 128;
    int n0 = blockIdx.x * 128;
    int lr = tid >> 1;
    int lc = (tid & 1) * 4;
    int tx = tid & 15, ty = tid >> 4;
    float acc[8][8];
#pragma unroll
    for (int i = 0; i < 8; i++)
#pragma unroll
        for (int j = 0; j < 8; j++) acc[i][j] = 0.0f;

    const float* Ap = A + (long)(m0 + lr) * K + lc;
    const float* Wp = W + (long)(n0 + lr) * K + lc;
    for (int k0 = 0; k0 < K; k0 += 8) {
        float4 a4 = *(const float4*)(Ap + k0);
        float4 w4 = *(const float4*)(Wp + k0);
        __syncthreads();
        As[lc + 0][lr] = a4.x; As[lc + 1][lr] = a4.y;
        As[lc + 2][lr] = a4.z; As[lc + 3][lr] = a4.w;
        Ws[lc + 0][lr] = w4.x; Ws[lc + 1][lr] = w4.y;
        Ws[lc + 2][lr] = w4.z; Ws[lc + 3][lr] = w4.w;
        __syncthreads();
#pragma unroll
        for (int kk = 0; kk < 8; kk++) {
            float ar[8], br[8];
#pragma unroll
            for (int i = 0; i < 8; i++) ar[i] = As[kk][ty * 8 + i];
#pragma unroll
            for (int j = 0; j < 8; j++) br[j] = Ws[kk][tx * 8 + j];
#pragma unroll
            for (int i = 0; i < 8; i++)
#pragma unroll
                for (int j = 0; j < 8; j++) acc[i][j] += ar[i] * br[j];
        }
    }
#pragma unroll
    for (int i = 0; i < 8; i++) {
        int m = m0 + ty * 8 + i;
#pragma unroll
        for (int j = 0; j < 8; j++) {
            int n = n0 + tx * 8 + j;
            float v = acc[i][j] + bias[n];
            if (RESID) v += res[(long)m * N + n];
            if (GELU) v = 0.5f * v * (1.0f + erff(v * 0.70710678118654752f));
            out[(long)m * N + n] = v;
        }
    }
}

// ---------------- fused LIF attention ----------------
// 16 queries per block (16 warps / 512 threads), K/V tiles of 64 rows in smem.
// Pass 1: online softmax max/Z.  Pass 2: recompute s, LIF-gate, renormalize, PV.
__global__ __launch_bounds__(512) void attn_kernel(
    const float* __restrict__ qkv, float* __restrict__ y,
    const float* __restrict__ thr, const float* __restrict__ leak,
    const float* __restrict__ steep) {
    __shared__ float qs[16][64];
    __shared__ float Ks[64][65];
    __shared__ float Vs[64][65];
    __shared__ float modbuf[16][64];

    int b = blockIdx.z, hh = blockIdx.y;
    int q0 = blockIdx.x * 16;
    int tid = threadIdx.x;
    int w = tid >> 5, lane = tid & 31;

    float th = fabsf(thr[hh]) * 0.1f;
    float lk = 1.0f / (1.0f + __expf(-leak[hh]));
    float sp_in = steep[hh];
    float st = (sp_in > 20.0f) ? sp_in : log1pf(__expf(sp_in));

    // load Q tile (16 x 64)
    for (int i = 0; i < 2; i++) {
        int e = tid + i * 512;
        int r = e >> 6, c = e & 63;
        qs[r][c] = qkv[((long)(b * Tt + q0 + r)) * 2304 + hh * 64 + c];
    }
    int qpos = q0 + w;
    int ntiles = (q0 + 15) / 64 + 1;
    const float scale = 0.125f;
    const long kbase = (long)b * Tt * 2304 + 768 + hh * 64;

    // ---- pass 1: max & Z (online, per-lane then warp merge) ----
    float mval = -INFINITY, zval = 0.0f;
    for (int kt = 0; kt < ntiles; kt++) {
        __syncthreads();
        for (int i = 0; i < 8; i++) {
            int e = tid + i * 512;
            int r = e >> 6, c = e & 63;
            Ks[r][c] = qkv[kbase + (long)(kt * 64 + r) * 2304 + c];
        }
        __syncthreads();
#pragma unroll
        for (int jj = 0; jj < 2; jj++) {
            int j = jj * 32 + lane;
            int kpos = kt * 64 + j;
            if (kpos <= qpos) {
                float s = 0.0f;
#pragma unroll
                for (int d = 0; d < 64; d++) s += qs[w][d] * Ks[j][d];
                s *= scale;
                float nm = fmaxf(mval, s);
                zval = zval * __expf(mval - nm) + __expf(s - nm);
                mval = nm;
            }
        }
    }
#pragma unroll
    for (int off = 16; off >= 1; off >>= 1) {
        float m2 = __shfl_xor_sync(0xffffffffu, mval, off);
        float z2 = __shfl_xor_sync(0xffffffffu, zval, off);
        float nm = fmaxf(mval, m2);
        float e1 = (mval == -INFINITY) ? 0.0f : __expf(mval - nm);
        float e2 = (m2 == -INFINITY) ? 0.0f : __expf(m2 - nm);
        zval = zval * e1 + z2 * e2;
        mval = nm;
    }
    float inv_z = 1.0f / zval;

    // ---- pass 2: LIF modulate + PV ----
    float acc0 = 0.0f, acc1 = 0.0f, smod = 0.0f;
    int d0 = lane * 2, d1 = lane * 2 + 1;
    for (int kt = 0; kt < ntiles; kt++) {
        __syncthreads();
        for (int i = 0; i < 8; i++) {
            int e = tid + i * 512;
            int r = e >> 6, c = e & 63;
            long row = kbase + (long)(kt * 64 + r) * 2304 + c;
            Ks[r][c] = qkv[row];
            Vs[r][c] = qkv[row + 768];
        }
        __syncthreads();
#pragma unroll
        for (int jj = 0; jj < 2; jj++) {
            int j = jj * 32 + lane;
            int kpos = kt * 64 + j;
            float mod = 0.0f;
            if (kpos <= qpos) {
                float s = 0.0f;
#pragma unroll
                for (int d = 0; d < 64; d++) s += qs[w][d] * Ks[j][d];
                s *= scale;
                float p = __expf(s - mval) * inv_z;
                float fire = 1.0f / (1.0f + __expf(-st * (p - th)));
                float wg = fire + lk * (1.0f - fire);
                mod = p * wg;
            }
            modbuf[w][j] = mod;
            smod += mod;
        }
        __syncwarp();
#pragma unroll 8
        for (int j = 0; j < 64; j++) {
            float mv = modbuf[w][j];
            acc0 += mv * Vs[j][d0];
            acc1 += mv * Vs[j][d1];
        }
    }
#pragma unroll
    for (int off = 16; off >= 1; off >>= 1)
        smod += __shfl_xor_sync(0xffffffffu, smod, off);
    float inv_s = 1.0f / (smod + 1e-8f);
    long yo = ((long)(b * Tt + qpos)) * Cc + hh * 64;
    y[yo + d0] = acc0 * inv_s;
    y[yo + d1] = acc1 * inv_s;
}

// ---------------- tied lm head: out[r, n] = dot(xl[r,:], wte[n,:]) ----------------
__global__ __launch_bounds__(256) void lmhead_kernel(const float* __restrict__ wte,
                                                     float* __restrict__ out) {
    __shared__ float xs[Bb * Cc];
    int tid = threadIdx.x;
    for (int i = tid; i < Bb * Cc; i += 256) xs[i] = g_xl[i];
    __syncthreads();
    int warp = tid >> 5, lane = tid & 31;
    int n = blockIdx.x * 8 + warp;
    if (n >= Vv) return;
    float acc[Bb];
#pragma unroll
    for (int r = 0; r < Bb; r++) acc[r] = 0.0f;
    const float* wrow = wte + (long)n * Cc;
    for (int k = lane; k < Cc; k += 32) {
        float wv = wrow[k];
#pragma unroll
        for (int r = 0; r < Bb; r++) acc[r] += wv * xs[r * Cc + k];
    }
#pragma unroll
    for (int r = 0; r < Bb; r++)
#pragma unroll
        for (int off = 16; off >= 1; off >>= 1)
            acc[r] += __shfl_xor_sync(0xffffffffu, acc[r], off);
    if (lane == 0) {
#pragma unroll
        for (int r = 0; r < Bb; r++) out[(long)r * Vv + n] = acc[r];
    }
}

// ---------------- lnf into g_xl (8 last-position rows) ----------------
// reuse ln_kernel with stride Tt*Cc and offset (Tt-1)*Cc.

extern "C" void kernel_launch(void* const* d_in, const int* in_sizes, int n_in,
                              void* d_out, int out_size) {
    const int* idx      = (const int*)d_in[0];
    const float* wte    = (const float*)d_in[1];
    const float* wpe    = (const float*)d_in[2];
    const float* ln1_w  = (const float*)d_in[3];
    const float* ln1_b  = (const float*)d_in[4];
    const float* attn_w = (const float*)d_in[5];
    const float* attn_b = (const float*)d_in[6];
    const float* proj_w = (const float*)d_in[7];
    const float* proj_b = (const float*)d_in[8];
    const float* thr    = (const float*)d_in[9];
    const float* leak   = (const float*)d_in[10];
    const float* steep  = (const float*)d_in[11];
    const float* ln2_w  = (const float*)d_in[12];
    const float* ln2_b  = (const float*)d_in[13];
    const float* fc_w   = (const float*)d_in[14];
    const float* fc_b   = (const float*)d_in[15];
    const float* mproj_w= (const float*)d_in[16];
    const float* mproj_b= (const float*)d_in[17];
    const float* lnf_w  = (const float*)d_in[18];
    const float* lnf_b  = (const float*)d_in[19];
    float* out = (float*)d_out;

    float *px, *ph, *py, *pqkv, *pm, *pxl;
    cudaGetSymbolAddress((void**)&px, g_x);
    cudaGetSymbolAddress((void**)&ph, g_h);
    cudaGetSymbolAddress((void**)&py, g_y);
    cudaGetSymbolAddress((void**)&pqkv, g_qkv);
    cudaGetSymbolAddress((void**)&pm, g_m);
    cudaGetSymbolAddress((void**)&pxl, g_xl);

    const int Mrows = Bb * Tt;  // 8192

    embed_kernel<<<(Bb * Tt * Cc + 255) / 256, 256>>>(idx, wte, wpe);

    for (int l = 0; l < Ll; l++) {
        // ln1
        ln_kernel<<<Mrows, 256>>>(px, ph, ln1_w + l * Cc, ln1_b + l * Cc, Cc, 0);
        // qkv = h @ attn_w^T + attn_b
        {
            dim3 grid(3 * Cc / 128, Mrows / 128);
            sgemm_kernel<false, false><<<grid, 256>>>(
                ph, attn_w + (long)l * 3 * Cc * Cc, attn_b + l * 3 * Cc,
                nullptr, pqkv, Mrows, 3 * Cc, Cc);
        }
        // attention
        {
            dim3 grid(Tt / 16, Hh, Bb);
            attn_kernel<<<grid, 512>>>(pqkv, py, thr + l * Hh, leak + l * Hh,
                                       steep + l * Hh);
        }
        // x = x + y @ proj_w^T + proj_b
        {
            dim3 grid(Cc / 128, Mrows / 128);
            sgemm_kernel<false, true><<<grid, 256>>>(
                py, proj_w + (long)l * Cc * Cc, proj_b + l * Cc, px, px,
                Mrows, Cc, Cc);
        }
        // ln2
        ln_kernel<<<Mrows, 256>>>(px, ph, ln2_w + l * Cc, ln2_b + l * Cc, Cc, 0);
        // m = gelu(h @ fc_w^T + fc_b)
        {
            dim3 grid(4 * Cc / 128, Mrows / 128);
            sgemm_kernel<true, false><<<grid, 256>>>(
                ph, fc_w + (long)l * 4 * Cc * Cc, fc_b + l * 4 * Cc, nullptr,
                pm, Mrows, 4 * Cc, Cc);
        }
        // x = x + m @ mproj_w^T + mproj_b
        {
            dim3 grid(Cc / 128, Mrows / 128);
            sgemm_kernel<false, true><<<grid, 256>>>(
                pm, mproj_w + (long)l * Cc * 4 * Cc, mproj_b + l * Cc, px, px,
                Mrows, Cc, 4 * Cc);
        }
    }

    // lnf on last position of each batch row
    ln_kernel<<<Bb, 256>>>(px, pxl, lnf_w, lnf_b, (long)Tt * Cc,
                           (long)(Tt - 1) * Cc);
    // logits = xl @ wte^T
    lmhead_kernel<<<(Vv + 7) / 8, 256>>>(wte, out);
}

// round 16
// speedup vs baseline: 1.0624x; 1.0617x over previous
#include <cuda_runtime.h>
#include <math.h>
#include <stdint.h>

#define Bb 8
#define Tt 1024
#define Cc 768
#define Hh 12
#define Dd 64
#define Ll 6
#define Vv 50257

// ---------------- scratch (no allocations allowed) ----------------
__device__ __align__(16) float g_x[Bb * Tt * Cc];        // residual stream
__device__ __align__(16) float g_h[Bb * Tt * Cc];        // ln output
__device__ __align__(16) float g_y[Bb * Tt * Cc];        // attn output
__device__ __align__(16) float g_qkv[Bb * Tt * 3 * Cc];  // qkv
__device__ __align__(16) float g_m[Bb * Tt * 4 * Cc];    // mlp hidden
__device__ __align__(16) float g_xl[Bb * Cc];            // lnf(last pos)

// ---------------- tf32 helpers (portable PTX, no 'a'-gated instrs) ------
__device__ __forceinline__ uint32_t f2tf32(float x) {
    uint32_t r;
    asm("cvt.rna.tf32.f32 %0, %1;" : "=r"(r) : "f"(x));
    return r;
}

// mma.sync m16n8k8 tf32: D += A*B (acc in-place)
__device__ __forceinline__ void mma_tf32(float* c, uint32_t a0, uint32_t a1,
                                         uint32_t a2, uint32_t a3,
                                         uint32_t b0, uint32_t b1) {
    asm volatile(
        "mma.sync.aligned.m16n8k8.row.col.f32.tf32.tf32.f32 "
        "{%0,%1,%2,%3}, {%4,%5,%6,%7}, {%8,%9}, {%0,%1,%2,%3};"
        : "+f"(c[0]), "+f"(c[1]), "+f"(c[2]), "+f"(c[3])
        : "r"(a0), "r"(a1), "r"(a2), "r"(a3), "r"(b0), "r"(b1));
}

// ---------------- tf32 split GEMM via mma.sync ----------------
// out[m,n] = sum_k A[m,k]*W[n,k] + bias[n] (+res) (+gelu)
// BM=BN=128, BK=16, 256 threads, warps 2(M)x4(N), warp tile 64x32.
// SMEM per stage: A2[128][20] float2(hi,lo), B2[128][20] float2 -> 40960 B.
#define F2_STRIDE 20
#define STAGE_F2 (2 * 128 * F2_STRIDE)              // 5120 float2 per stage
#define GEMM_SMEM_BYTES (2 * STAGE_F2 * 8)          // 81920 bytes

template <bool GELU, bool RESID>
__global__ __launch_bounds__(256, 1) void mm_kernel(
    const float* __restrict__ A, const float* __restrict__ W,
    const float* __restrict__ bias, const float* __restrict__ res,
    float* __restrict__ out, int M, int N, int K) {
    extern __shared__ float2 sm2[];
    const int tid = threadIdx.x;
    const int lane = tid & 31;
    const int wid = tid >> 5;
    const int g = lane >> 2;     // groupID
    const int t = lane & 3;      // threadID_in_group
    const int warp_m = wid & 1;  // 0..1
    const int warp_n = wid >> 1; // 0..3
    const int rm = warp_m * 64;
    const int cn = warp_n * 32;
    const int m0 = blockIdx.y * 128;
    const int n0 = blockIdx.x * 128;

    const int nch = K >> 4;

    // staging thread mapping: float4 id f: row=f>>2, col4=f&3 (16 floats/row)
    const int r0 = tid >> 2, c40 = (tid & 3);          // f = tid
    const int r1 = (tid + 256) >> 2, c41 = c40;        // f = tid+256 (same low bits)

    float4 ra0, ra1, rb0, rb1;
    const float* Abase = A + (long)(m0)*K;
    const float* Wbase = W + (long)(n0)*K;

    auto ldg_tile = [&](int kt) {
        int kc = kt * 16;
        ra0 = *(const float4*)(Abase + (long)r0 * K + kc + c40 * 4);
        ra1 = *(const float4*)(Abase + (long)r1 * K + kc + c41 * 4);
        rb0 = *(const float4*)(Wbase + (long)r0 * K + kc + c40 * 4);
        rb1 = *(const float4*)(Wbase + (long)r1 * K + kc + c41 * 4);
    };

    auto split_store = [&](float2* dst, const float4& v) {
        // interleave (hi,lo) per element: 4 float2 = 2 float4 stores
        float hx = __uint_as_float(f2tf32(v.x));
        float hy = __uint_as_float(f2tf32(v.y));
        float hz = __uint_as_float(f2tf32(v.z));
        float hw = __uint_as_float(f2tf32(v.w));
        float lx = __uint_as_float(f2tf32(v.x - hx));
        float ly = __uint_as_float(f2tf32(v.y - hy));
        float lz = __uint_as_float(f2tf32(v.z - hz));
        float lw = __uint_as_float(f2tf32(v.w - hw));
        float4* p = (float4*)dst;
        p[0] = make_float4(hx, lx, hy, ly);
        p[1] = make_float4(hz, lz, hw, lw);
    };

    auto sts_tile = [&](int s) {
        float2* sA = sm2 + s * STAGE_F2;
        float2* sB = sA + 128 * F2_STRIDE;
        split_store(&sA[r0 * F2_STRIDE + c40 * 4], ra0);
        split_store(&sA[r1 * F2_STRIDE + c41 * 4], ra1);
        split_store(&sB[r0 * F2_STRIDE + c40 * 4], rb0);
        split_store(&sB[r1 * F2_STRIDE + c41 * 4], rb1);
    };

    float acc[4][4][4];
#pragma unroll
    for (int i = 0; i < 4; i++)
#pragma unroll
        for (int j = 0; j < 4; j++)
#pragma unroll
            for (int q = 0; q < 4; q++) acc[i][j][q] = 0.0f;

    ldg_tile(0);
    sts_tile(0);
    __syncthreads();

    for (int it = 0; it < nch; it++) {
        if (it + 1 < nch) ldg_tile(it + 1);

        const float2* sA = sm2 + (it & 1) * STAGE_F2;
        const float2* sB = sA + 128 * F2_STRIDE;
#pragma unroll
        for (int ks = 0; ks < 2; ks++) {
            int kof = ks * 8;
            // A fragments: a0=(r,t) a1=(r+8,t) a2=(r,t+4) a3=(r+8,t+4)
            float2 af[4][4];
#pragma unroll
            for (int i = 0; i < 4; i++) {
                int r = rm + i * 16 + g;
                af[i][0] = sA[r * F2_STRIDE + kof + t];
                af[i][1] = sA[(r + 8) * F2_STRIDE + kof + t];
                af[i][2] = sA[r * F2_STRIDE + kof + t + 4];
                af[i][3] = sA[(r + 8) * F2_STRIDE + kof + t + 4];
            }
            // B fragments: b0=(k=t, n) b1=(k=t+4, n)
            float2 bf[4][2];
#pragma unroll
            for (int j = 0; j < 4; j++) {
                int n = cn + j * 8 + g;
                bf[j][0] = sB[n * F2_STRIDE + kof + t];
                bf[j][1] = sB[n * F2_STRIDE + kof + t + 4];
            }
#pragma unroll
            for (int i = 0; i < 4; i++) {
                uint32_t ah0 = __float_as_uint(af[i][0].x);
                uint32_t ah1 = __float_as_uint(af[i][1].x);
                uint32_t ah2 = __float_as_uint(af[i][2].x);
                uint32_t ah3 = __float_as_uint(af[i][3].x);
                uint32_t al0 = __float_as_uint(af[i][0].y);
                uint32_t al1 = __float_as_uint(af[i][1].y);
                uint32_t al2 = __float_as_uint(af[i][2].y);
                uint32_t al3 = __float_as_uint(af[i][3].y);
#pragma unroll
                for (int j = 0; j < 4; j++) {
                    uint32_t bh0 = __float_as_uint(bf[j][0].x);
                    uint32_t bh1 = __float_as_uint(bf[j][1].x);
                    uint32_t bl0 = __float_as_uint(bf[j][0].y);
                    uint32_t bl1 = __float_as_uint(bf[j][1].y);
                    mma_tf32(acc[i][j], ah0, ah1, ah2, ah3, bh0, bh1);
                    mma_tf32(acc[i][j], ah0, ah1, ah2, ah3, bl0, bl1);
                    mma_tf32(acc[i][j], al0, al1, al2, al3, bh0, bh1);
                }
            }
        }

        if (it + 1 < nch) sts_tile((it + 1) & 1);
        __syncthreads();
    }

    // epilogue: c0,c1 at (row=g, col=2t,2t+1); c2,c3 at row=g+8
#pragma unroll
    for (int i = 0; i < 4; i++) {
        int row0 = m0 + rm + i * 16 + g;
        int row1 = row0 + 8;
#pragma unroll
        for (int j = 0; j < 4; j++) {
            int col = n0 + cn + j * 8 + t * 2;
            float2 bv = *(const float2*)(bias + col);
            float2 v0 = make_float2(acc[i][j][0] + bv.x, acc[i][j][1] + bv.y);
            float2 v1 = make_float2(acc[i][j][2] + bv.x, acc[i][j][3] + bv.y);
            if (RESID) {
                float2 r0v = *(const float2*)(res + (long)row0 * N + col);
                float2 r1v = *(const float2*)(res + (long)row1 * N + col);
                v0.x += r0v.x; v0.y += r0v.y;
                v1.x += r1v.x; v1.y += r1v.y;
            }
            if (GELU) {
                v0.x = 0.5f * v0.x * (1.0f + erff(v0.x * 0.70710678118654752f));
                v0.y = 0.5f * v0.y * (1.0f + erff(v0.y * 0.70710678118654752f));
                v1.x = 0.5f * v1.x * (1.0f + erff(v1.x * 0.70710678118654752f));
                v1.y = 0.5f * v1.y * (1.0f + erff(v1.y * 0.70710678118654752f));
            }
            *(float2*)(out + (long)row0 * N + col) = v0;
            *(float2*)(out + (long)row1 * N + col) = v1;
        }
    }
}

// ---------------- embedding ----------------
__global__ void embed_kernel(const int* __restrict__ idx,
                             const float* __restrict__ wte,
                             const float* __restrict__ wpe) {
    int i = blockIdx.x * blockDim.x + threadIdx.x;
    if (i >= Bb * Tt * Cc) return;
    int c = i % Cc;
    int bt = i / Cc;
    int t = bt % Tt;
    g_x[i] = wte[(long)idx[bt] * Cc + c] + wpe[t * Cc + c];
}

// ---------------- layernorm (one block per row, C=768) ----------------
__global__ __launch_bounds__(256) void ln_kernel(const float* __restrict__ in,
                                                 float* __restrict__ out,
                                                 const float* __restrict__ w,
                                                 const float* __restrict__ b,
                                                 long in_stride, long in_off) {
    int r = blockIdx.x;
    int tid = threadIdx.x;
    const float* xr = in + (long)r * in_stride + in_off;
    float v0 = xr[tid], v1 = xr[tid + 256], v2 = xr[tid + 512];
    __shared__ float red[256];
    red[tid] = v0 + v1 + v2;
    __syncthreads();
    for (int off = 128; off; off >>= 1) {
        if (tid < off) red[tid] += red[tid + off];
        __syncthreads();
    }
    float mean = red[0] * (1.0f / 768.0f);
    __syncthreads();
    float d0 = v0 - mean, d1 = v1 - mean, d2 = v2 - mean;
    red[tid] = d0 * d0 + d1 * d1 + d2 * d2;
    __syncthreads();
    for (int off = 128; off; off >>= 1) {
        if (tid < off) red[tid] += red[tid + off];
        __syncthreads();
    }
    float rstd = rsqrtf(red[0] * (1.0f / 768.0f) + 1e-5f);
    float* orow = out + (long)r * Cc;
    orow[tid]       = d0 * rstd * w[tid]       + b[tid];
    orow[tid + 256] = d1 * rstd * w[tid + 256] + b[tid + 256];
    orow[tid + 512] = d2 * rstd * w[tid + 512] + b[tid + 512];
}

// ---------------- fused LIF attention (unchanged) ----------------
__global__ __launch_bounds__(512) void attn_kernel(
    const float* __restrict__ qkv, float* __restrict__ y,
    const float* __restrict__ thr, const float* __restrict__ leak,
    const float* __restrict__ steep) {
    __shared__ float qs[16][64];
    __shared__ float Ks[64][65];
    __shared__ float Vs[64][65];
    __shared__ float modbuf[16][64];

    int b = blockIdx.z, hh = blockIdx.y;
    int q0 = blockIdx.x * 16;
    int tid = threadIdx.x;
    int w = tid >> 5, lane = tid & 31;

    float th = fabsf(thr[hh]) * 0.1f;
    float lk = 1.0f / (1.0f + __expf(-leak[hh]));
    float sp_in = steep[hh];
    float st = (sp_in > 20.0f) ? sp_in : log1pf(__expf(sp_in));

    for (int i = 0; i < 2; i++) {
        int e = tid + i * 512;
        int r = e >> 6, c = e & 63;
        qs[r][c] = qkv[((long)(b * Tt + q0 + r)) * 2304 + hh * 64 + c];
    }
    int qpos = q0 + w;
    int ntiles = (q0 + 15) / 64 + 1;
    const float scale = 0.125f;
    const long kbase = (long)b * Tt * 2304 + 768 + hh * 64;

    float mval = -INFINITY, zval = 0.0f;
    for (int kt = 0; kt < ntiles; kt++) {
        __syncthreads();
        for (int i = 0; i < 8; i++) {
            int e = tid + i * 512;
            int r = e >> 6, c = e & 63;
            Ks[r][c] = qkv[kbase + (long)(kt * 64 + r) * 2304 + c];
        }
        __syncthreads();
#pragma unroll
        for (int jj = 0; jj < 2; jj++) {
            int j = jj * 32 + lane;
            int kpos = kt * 64 + j;
            if (kpos <= qpos) {
                float s = 0.0f;
#pragma unroll
                for (int d = 0; d < 64; d++) s += qs[w][d] * Ks[j][d];
                s *= scale;
                float nm = fmaxf(mval, s);
                zval = zval * __expf(mval - nm) + __expf(s - nm);
                mval = nm;
            }
        }
    }
#pragma unroll
    for (int off = 16; off >= 1; off >>= 1) {
        float m2 = __shfl_xor_sync(0xffffffffu, mval, off);
        float z2 = __shfl_xor_sync(0xffffffffu, zval, off);
        float nm = fmaxf(mval, m2);
        float e1 = (mval == -INFINITY) ? 0.0f : __expf(mval - nm);
        float e2 = (m2 == -INFINITY) ? 0.0f : __expf(m2 - nm);
        zval = zval * e1 + z2 * e2;
        mval = nm;
    }
    float inv_z = 1.0f / zval;

    float acc0 = 0.0f, acc1 = 0.0f, smod = 0.0f;
    int d0 = lane * 2, d1 = lane * 2 + 1;
    for (int kt = 0; kt < ntiles; kt++) {
        __syncthreads();
        for (int i = 0; i < 8; i++) {
            int e = tid + i * 512;
            int r = e >> 6, c = e & 63;
            long row = kbase + (long)(kt * 64 + r) * 2304 + c;
            Ks[r][c] = qkv[row];
            Vs[r][c] = qkv[row + 768];
        }
        __syncthreads();
#pragma unroll
        for (int jj = 0; jj < 2; jj++) {
            int j = jj * 32 + lane;
            int kpos = kt * 64 + j;
            float mod = 0.0f;
            if (kpos <= qpos) {
                float s = 0.0f;
#pragma unroll
                for (int d = 0; d < 64; d++) s += qs[w][d] * Ks[j][d];
                s *= scale;
                float p = __expf(s - mval) * inv_z;
                float fire = 1.0f / (1.0f + __expf(-st * (p - th)));
                float wg = fire + lk * (1.0f - fire);
                mod = p * wg;
            }
            modbuf[w][j] = mod;
            smod += mod;
        }
        __syncwarp();
#pragma unroll 8
        for (int j = 0; j < 64; j++) {
            float mv = modbuf[w][j];
            acc0 += mv * Vs[j][d0];
            acc1 += mv * Vs[j][d1];
        }
    }
#pragma unroll
    for (int off = 16; off >= 1; off >>= 1)
        smod += __shfl_xor_sync(0xffffffffu, smod, off);
    float inv_s = 1.0f / (smod + 1e-8f);
    long yo = ((long)(b * Tt + qpos)) * Cc + hh * 64;
    y[yo + d0] = acc0 * inv_s;
    y[yo + d1] = acc1 * inv_s;
}

// ---------------- tied lm head ----------------
__global__ __launch_bounds__(256) void lmhead_kernel(const float* __restrict__ wte,
                                                     float* __restrict__ out) {
    __shared__ float xs[Bb * Cc];
    int tid = threadIdx.x;
    for (int i = tid; i < Bb * Cc; i += 256) xs[i] = g_xl[i];
    __syncthreads();
    int warp = tid >> 5, lane = tid & 31;
    int n = blockIdx.x * 8 + warp;
    if (n >= Vv) return;
    float acc[Bb];
#pragma unroll
    for (int r = 0; r < Bb; r++) acc[r] = 0.0f;
    const float* wrow = wte + (long)n * Cc;
    for (int k = lane; k < Cc; k += 32) {
        float wv = wrow[k];
#pragma unroll
        for (int r = 0; r < Bb; r++) acc[r] += wv * xs[r * Cc + k];
    }
#pragma unroll
    for (int r = 0; r < Bb; r++)
#pragma unroll
        for (int off = 16; off >= 1; off >>= 1)
            acc[r] += __shfl_xor_sync(0xffffffffu, acc[r], off);
    if (lane == 0) {
#pragma unroll
        for (int r = 0; r < Bb; r++) out[(long)r * Vv + n] = acc[r];
    }
}

extern "C" void kernel_launch(void* const* d_in, const int* in_sizes, int n_in,
                              void* d_out, int out_size) {
    const int* idx      = (const int*)d_in[0];
    const float* wte    = (const float*)d_in[1];
    const float* wpe    = (const float*)d_in[2];
    const float* ln1_w  = (const float*)d_in[3];
    const float* ln1_b  = (const float*)d_in[4];
    const float* attn_w = (const float*)d_in[5];
    const float* attn_b = (const float*)d_in[6];
    const float* proj_w = (const float*)d_in[7];
    const float* proj_b = (const float*)d_in[8];
    const float* thr    = (const float*)d_in[9];
    const float* leak   = (const float*)d_in[10];
    const float* steep  = (const float*)d_in[11];
    const float* ln2_w  = (const float*)d_in[12];
    const float* ln2_b  = (const float*)d_in[13];
    const float* fc_w   = (const float*)d_in[14];
    const float* fc_b   = (const float*)d_in[15];
    const float* mproj_w= (const float*)d_in[16];
    const float* mproj_b= (const float*)d_in[17];
    const float* lnf_w  = (const float*)d_in[18];
    const float* lnf_b  = (const float*)d_in[19];
    float* out = (float*)d_out;

    float *px, *ph, *py, *pqkv, *pm, *pxl;
    cudaGetSymbolAddress((void**)&px, g_x);
    cudaGetSymbolAddress((void**)&ph, g_h);
    cudaGetSymbolAddress((void**)&py, g_y);
    cudaGetSymbolAddress((void**)&pqkv, g_qkv);
    cudaGetSymbolAddress((void**)&pm, g_m);
    cudaGetSymbolAddress((void**)&pxl, g_xl);

    cudaFuncSetAttribute(mm_kernel<false, false>,
                         cudaFuncAttributeMaxDynamicSharedMemorySize, GEMM_SMEM_BYTES);
    cudaFuncSetAttribute(mm_kernel<false, true>,
                         cudaFuncAttributeMaxDynamicSharedMemorySize, GEMM_SMEM_BYTES);
    cudaFuncSetAttribute(mm_kernel<true, false>,
                         cudaFuncAttributeMaxDynamicSharedMemorySize, GEMM_SMEM_BYTES);

    const int Mrows = Bb * Tt;  // 8192

    embed_kernel<<<(Bb * Tt * Cc + 255) / 256, 256>>>(idx, wte, wpe);

    for (int l = 0; l < Ll; l++) {
        // ln1
        ln_kernel<<<Mrows, 256>>>(px, ph, ln1_w + l * Cc, ln1_b + l * Cc, Cc, 0);
        // qkv = h @ attn_w^T + attn_b
        {
            dim3 grid(3 * Cc / 128, Mrows / 128);
            mm_kernel<false, false><<<grid, 256, GEMM_SMEM_BYTES>>>(
                ph, attn_w + (long)l * 3 * Cc * Cc, attn_b + l * 3 * Cc,
                pqkv, pqkv, Mrows, 3 * Cc, Cc);
        }
        // attention
        {
            dim3 grid(Tt / 16, Hh, Bb);
            attn_kernel<<<grid, 512>>>(pqkv, py, thr + l * Hh, leak + l * Hh,
                                       steep + l * Hh);
        }
        // x = x + y @ proj_w^T + proj_b
        {
            dim3 grid(Cc / 128, Mrows / 128);
            mm_kernel<false, true><<<grid, 256, GEMM_SMEM_BYTES>>>(
                py, proj_w + (long)l * Cc * Cc, proj_b + l * Cc, px, px,
                Mrows, Cc, Cc);
        }
        // ln2
        ln_kernel<<<Mrows, 256>>>(px, ph, ln2_w + l * Cc, ln2_b + l * Cc, Cc, 0);
        // m = gelu(h @ fc_w^T + fc_b)
        {
            dim3 grid(4 * Cc / 128, Mrows / 128);
            mm_kernel<true, false><<<grid, 256, GEMM_SMEM_BYTES>>>(
                ph, fc_w + (long)l * 4 * Cc * Cc, fc_b + l * 4 * Cc, pm,
                pm, Mrows, 4 * Cc, Cc);
        }
        // x = x + m @ mproj_w^T + mproj_b
        {
            dim3 grid(Cc / 128, Mrows / 128);
            mm_kernel<false, true><<<grid, 256, GEMM_SMEM_BYTES>>>(
                pm, mproj_w + (long)l * Cc * 4 * Cc, mproj_b + l * Cc, px, px,
                Mrows, Cc, 4 * Cc);
        }
    }

    // lnf on last position of each batch row
    ln_kernel<<<Bb, 256>>>(px, pxl, lnf_w, lnf_b, (long)Tt * Cc,
                           (long)(Tt - 1) * Cc);
    // logits = xl @ wte^T
    lmhead_kernel<<<(Vv + 7) / 8, 256>>>(wte, out);
}

// round 17
// speedup vs baseline: 1.7222x; 1.6211x over previous
#include <cuda_runtime.h>
#include <cuda_fp16.h>
#include <math.h>
#include <stdint.h>

#define Bb 8
#define Tt 1024
#define Cc 768
#define Hh 12
#define Dd 64
#define Ll 6
#define Vv 50257

// ---------------- scratch (no allocations allowed) ----------------
__device__ __align__(16) float g_x[Bb * Tt * Cc];        // residual stream
__device__ __align__(16) float g_h[Bb * Tt * Cc];        // ln output
__device__ __align__(16) float g_y[Bb * Tt * Cc];        // attn output
__device__ __align__(16) float g_qkv[Bb * Tt * 3 * Cc];  // qkv
__device__ __align__(16) float g_m[Bb * Tt * 4 * Cc];    // mlp hidden
__device__ __align__(16) float g_xl[Bb * Cc];            // lnf(last pos)

// ---------------- portable PTX helpers (sm_80+, no 'a'-gated instrs) ----
__device__ __forceinline__ void ldsm4(uint32_t& r0, uint32_t& r1, uint32_t& r2,
                                      uint32_t& r3, uint32_t addr) {
    asm volatile(
        "ldmatrix.sync.aligned.m8n8.x4.shared.b16 {%0,%1,%2,%3}, [%4];"
        : "=r"(r0), "=r"(r1), "=r"(r2), "=r"(r3) : "r"(addr));
}

__device__ __forceinline__ void mma_f16(float* c, uint32_t a0, uint32_t a1,
                                        uint32_t a2, uint32_t a3,
                                        uint32_t b0, uint32_t b1) {
    asm volatile(
        "mma.sync.aligned.m16n8k16.row.col.f32.f16.f16.f32 "
        "{%0,%1,%2,%3}, {%4,%5,%6,%7}, {%8,%9}, {%0,%1,%2,%3};"
        : "+f"(c[0]), "+f"(c[1]), "+f"(c[2]), "+f"(c[3])
        : "r"(a0), "r"(a1), "r"(a2), "r"(a3), "r"(b0), "r"(b1));
}

// ---------------- fp16x3 split GEMM via mma.sync m16n8k16 ----------------
// out[m,n] = sum_k A[m,k]*W[n,k] + bias[n] (+res) (+gelu)
// BM=BN=128, BK=32, 256 threads, warps 2(M)x4(N), warp tile 64x32.
// SMEM per stage: 4 planes (Ahi, Alo, Bhi, Blo), each 128 rows x 40 halfs.
#define ROW_H 40                        // padded halfs per row (80 bytes)
#define PLANE_B (128 * ROW_H * 2)       // 10240 bytes
#define STAGE_B (4 * PLANE_B)           // 40960 bytes
#define GEMM_SMEM_BYTES (2 * STAGE_B)   // 81920 bytes

template <bool GELU, bool RESID>
__global__ __launch_bounds__(256, 1) void mm_kernel(
    const float* __restrict__ A, const float* __restrict__ W,
    const float* __restrict__ bias, const float* __restrict__ res,
    float* __restrict__ out, int M, int N, int K) {
    extern __shared__ __align__(16) char smem[];
    const uint32_t sb = (uint32_t)__cvta_generic_to_shared(smem);
    const int tid = threadIdx.x;
    const int lane = tid & 31;
    const int wid = tid >> 5;
    const int g = lane >> 2;
    const int t = lane & 3;
    const int rm = (wid & 1) * 64;   // warp M offset
    const int cn = (wid >> 1) * 32;  // warp N offset
    const int m0 = blockIdx.y * 128;
    const int n0 = blockIdx.x * 128;

    const int nst = K >> 5;  // stages of BK=32

    // ldmatrix lane offsets (bytes)
    const uint32_t a_off = (lane & 15) * 80 + (lane >> 4) * 16;
    const uint32_t b_off = ((lane & 7) + ((lane >> 4) << 3)) * 80 +
                           ((lane >> 3) & 1) * 16;

    // staging mapping: f = tid + i*256 -> row = f>>3 (0..127), c4 = f&7
    float4 ra[4], rb[4];
    const float* Abase = A + (long)m0 * K;
    const float* Wbase = W + (long)n0 * K;

    auto ldg_tile = [&](int st) {
        int kc = st * 32;
#pragma unroll
        for (int i = 0; i < 4; i++) {
            int f = tid + i * 256;
            int row = f >> 3, c4 = f & 7;
            ra[i] = *(const float4*)(Abase + (long)row * K + kc + c4 * 4);
            rb[i] = *(const float4*)(Wbase + (long)row * K + kc + c4 * 4);
        }
    };

    auto split_store = [&](uint32_t hi_addr, const float4& v) {
        // hi plane at hi_addr, lo plane at hi_addr + PLANE_B
        float hx_f, hy_f, hz_f, hw_f;
        __half hx = __float2half_rn(v.x); hx_f = __half2float(hx);
        __half hy = __float2half_rn(v.y); hy_f = __half2float(hy);
        __half hz = __float2half_rn(v.z); hz_f = __half2float(hz);
        __half hw = __float2half_rn(v.w); hw_f = __half2float(hw);
        __half2 h0 = __halves2half2(hx, hy);
        __half2 h1 = __halves2half2(hz, hw);
        __half2 l0 = __floats2half2_rn(v.x - hx_f, v.y - hy_f);
        __half2 l1 = __floats2half2_rn(v.z - hz_f, v.w - hw_f);
        uint32_t u0 = *reinterpret_cast<uint32_t*>(&h0);
        uint32_t u1 = *reinterpret_cast<uint32_t*>(&h1);
        uint32_t u2 = *reinterpret_cast<uint32_t*>(&l0);
        uint32_t u3 = *reinterpret_cast<uint32_t*>(&l1);
        asm volatile("st.shared.v2.b32 [%0], {%1,%2};" :: "r"(hi_addr),
                     "r"(u0), "r"(u1) : "memory");
        asm volatile("st.shared.v2.b32 [%0], {%1,%2};" :: "r"(hi_addr + PLANE_B),
                     "r"(u2), "r"(u3) : "memory");
    };

    auto sts_tile = [&](int s) {
        uint32_t stage = sb + s * STAGE_B;
#pragma unroll
        for (int i = 0; i < 4; i++) {
            int f = tid + i * 256;
            int row = f >> 3, c4 = f & 7;
            uint32_t off = row * 80 + c4 * 8;
            split_store(stage + off, ra[i]);                 // A hi/lo
            split_store(stage + 2 * PLANE_B + off, rb[i]);   // B hi/lo
        }
    };

    float acc[4][4][4];
#pragma unroll
    for (int i = 0; i < 4; i++)
#pragma unroll
        for (int j = 0; j < 4; j++)
#pragma unroll
            for (int q = 0; q < 4; q++) acc[i][j][q] = 0.0f;

    ldg_tile(0);
    sts_tile(0);
    __syncthreads();

    for (int it = 0; it < nst; it++) {
        if (it + 1 < nst) ldg_tile(it + 1);

        uint32_t stage = sb + (it & 1) * STAGE_B;
#pragma unroll
        for (int kk = 0; kk < 2; kk++) {
            uint32_t ah[4][4], al[4][4], bh[2][4], bl[2][4];
#pragma unroll
            for (int i = 0; i < 4; i++) {
                uint32_t off = (rm + 16 * i) * 80 + a_off + kk * 32;
                ldsm4(ah[i][0], ah[i][1], ah[i][2], ah[i][3], stage + off);
                ldsm4(al[i][0], al[i][1], al[i][2], al[i][3],
                      stage + PLANE_B + off);
            }
#pragma unroll
            for (int jp = 0; jp < 2; jp++) {
                uint32_t off = (cn + 16 * jp) * 80 + b_off + kk * 32;
                ldsm4(bh[jp][0], bh[jp][1], bh[jp][2], bh[jp][3],
                      stage + 2 * PLANE_B + off);
                ldsm4(bl[jp][0], bl[jp][1], bl[jp][2], bl[jp][3],
                      stage + 3 * PLANE_B + off);
            }
            // product pass 0: hi*hi, pass 1: hi*lo, pass 2: lo*hi
            // (same-acc MMAs are 16 instructions apart)
#pragma unroll
            for (int i = 0; i < 4; i++)
#pragma unroll
                for (int j = 0; j < 4; j++) {
                    int jp = j >> 1, jo = (j & 1) * 2;
                    mma_f16(acc[i][j], ah[i][0], ah[i][1], ah[i][2], ah[i][3],
                            bh[jp][jo], bh[jp][jo + 1]);
                }
#pragma unroll
            for (int i = 0; i < 4; i++)
#pragma unroll
                for (int j = 0; j < 4; j++) {
                    int jp = j >> 1, jo = (j & 1) * 2;
                    mma_f16(acc[i][j], ah[i][0], ah[i][1], ah[i][2], ah[i][3],
                            bl[jp][jo], bl[jp][jo + 1]);
                }
#pragma unroll
            for (int i = 0; i < 4; i++)
#pragma unroll
                for (int j = 0; j < 4; j++) {
                    int jp = j >> 1, jo = (j & 1) * 2;
                    mma_f16(acc[i][j], al[i][0], al[i][1], al[i][2], al[i][3],
                            bh[jp][jo], bh[jp][jo + 1]);
                }
        }

        if (it + 1 < nst) sts_tile((it + 1) & 1);
        __syncthreads();
    }

    // epilogue: c0,c1 at (row=g, col=2t,2t+1); c2,c3 at row=g+8
#pragma unroll
    for (int i = 0; i < 4; i++) {
        int row0 = m0 + rm + i * 16 + g;
        int row1 = row0 + 8;
#pragma unroll
        for (int j = 0; j < 4; j++) {
            int col = n0 + cn + j * 8 + t * 2;
            float2 bv = *(const float2*)(bias + col);
            float2 v0 = make_float2(acc[i][j][0] + bv.x, acc[i][j][1] + bv.y);
            float2 v1 = make_float2(acc[i][j][2] + bv.x, acc[i][j][3] + bv.y);
            if (RESID) {
                float2 r0v = *(const float2*)(res + (long)row0 * N + col);
                float2 r1v = *(const float2*)(res + (long)row1 * N + col);
                v0.x += r0v.x; v0.y += r0v.y;
                v1.x += r1v.x; v1.y += r1v.y;
            }
            if (GELU) {
                v0.x = 0.5f * v0.x * (1.0f + erff(v0.x * 0.70710678118654752f));
                v0.y = 0.5f * v0.y * (1.0f + erff(v0.y * 0.70710678118654752f));
                v1.x = 0.5f * v1.x * (1.0f + erff(v1.x * 0.70710678118654752f));
                v1.y = 0.5f * v1.y * (1.0f + erff(v1.y * 0.70710678118654752f));
            }
            *(float2*)(out + (long)row0 * N + col) = v0;
            *(float2*)(out + (long)row1 * N + col) = v1;
        }
    }
}

// ---------------- embedding ----------------
__global__ void embed_kernel(const int* __restrict__ idx,
                             const float* __restrict__ wte,
                             const float* __restrict__ wpe) {
    int i = blockIdx.x * blockDim.x + threadIdx.x;
    if (i >= Bb * Tt * Cc) return;
    int c = i % Cc;
    int bt = i / Cc;
    int t = bt % Tt;
    g_x[i] = wte[(long)idx[bt] * Cc + c] + wpe[t * Cc + c];
}

// ---------------- layernorm (one block per row, C=768) ----------------
__global__ __launch_bounds__(256) void ln_kernel(const float* __restrict__ in,
                                                 float* __restrict__ out,
                                                 const float* __restrict__ w,
                                                 const float* __restrict__ b,
                                                 long in_stride, long in_off) {
    int r = blockIdx.x;
    int tid = threadIdx.x;
    const float* xr = in + (long)r * in_stride + in_off;
    float v0 = xr[tid], v1 = xr[tid + 256], v2 = xr[tid + 512];
    __shared__ float red[256];
    red[tid] = v0 + v1 + v2;
    __syncthreads();
    for (int off = 128; off; off >>= 1) {
        if (tid < off) red[tid] += red[tid + off];
        __syncthreads();
    }
    float mean = red[0] * (1.0f / 768.0f);
    __syncthreads();
    float d0 = v0 - mean, d1 = v1 - mean, d2 = v2 - mean;
    red[tid] = d0 * d0 + d1 * d1 + d2 * d2;
    __syncthreads();
    for (int off = 128; off; off >>= 1) {
        if (tid < off) red[tid] += red[tid + off];
        __syncthreads();
    }
    float rstd = rsqrtf(red[0] * (1.0f / 768.0f) + 1e-5f);
    float* orow = out + (long)r * Cc;
    orow[tid]       = d0 * rstd * w[tid]       + b[tid];
    orow[tid + 256] = d1 * rstd * w[tid + 256] + b[tid + 256];
    orow[tid + 512] = d2 * rstd * w[tid + 512] + b[tid + 512];
}

// ---------------- fused LIF attention (unchanged) ----------------
__global__ __launch_bounds__(512) void attn_kernel(
    const float* __restrict__ qkv, float* __restrict__ y,
    const float* __restrict__ thr, const float* __restrict__ leak,
    const float* __restrict__ steep) {
    __shared__ float qs[16][64];
    __shared__ float Ks[64][65];
    __shared__ float Vs[64][65];
    __shared__ float modbuf[16][64];

    int b = blockIdx.z, hh = blockIdx.y;
    int q0 = blockIdx.x * 16;
    int tid = threadIdx.x;
    int w = tid >> 5, lane = tid & 31;

    float th = fabsf(thr[hh]) * 0.1f;
    float lk = 1.0f / (1.0f + __expf(-leak[hh]));
    float sp_in = steep[hh];
    float st = (sp_in > 20.0f) ? sp_in : log1pf(__expf(sp_in));

    for (int i = 0; i < 2; i++) {
        int e = tid + i * 512;
        int r = e >> 6, c = e & 63;
        qs[r][c] = qkv[((long)(b * Tt + q0 + r)) * 2304 + hh * 64 + c];
    }
    int qpos = q0 + w;
    int ntiles = (q0 + 15) / 64 + 1;
    const float scale = 0.125f;
    const long kbase = (long)b * Tt * 2304 + 768 + hh * 64;

    float mval = -INFINITY, zval = 0.0f;
    for (int kt = 0; kt < ntiles; kt++) {
        __syncthreads();
        for (int i = 0; i < 8; i++) {
            int e = tid + i * 512;
            int r = e >> 6, c = e & 63;
            Ks[r][c] = qkv[kbase + (long)(kt * 64 + r) * 2304 + c];
        }
        __syncthreads();
#pragma unroll
        for (int jj = 0; jj < 2; jj++) {
            int j = jj * 32 + lane;
            int kpos = kt * 64 + j;
            if (kpos <= qpos) {
                float s = 0.0f;
#pragma unroll
                for (int d = 0; d < 64; d++) s += qs[w][d] * Ks[j][d];
                s *= scale;
                float nm = fmaxf(mval, s);
                zval = zval * __expf(mval - nm) + __expf(s - nm);
                mval = nm;
            }
        }
    }
#pragma unroll
    for (int off = 16; off >= 1; off >>= 1) {
        float m2 = __shfl_xor_sync(0xffffffffu, mval, off);
        float z2 = __shfl_xor_sync(0xffffffffu, zval, off);
        float nm = fmaxf(mval, m2);
        float e1 = (mval == -INFINITY) ? 0.0f : __expf(mval - nm);
        float e2 = (m2 == -INFINITY) ? 0.0f : __expf(m2 - nm);
        zval = zval * e1 + z2 * e2;
        mval = nm;
    }
    float inv_z = 1.0f / zval;

    float acc0 = 0.0f, acc1 = 0.0f, smod = 0.0f;
    int d0 = lane * 2, d1 = lane * 2 + 1;
    for (int kt = 0; kt < ntiles; kt++) {
        __syncthreads();
        for (int i = 0; i < 8; i++) {
            int e = tid + i * 512;
            int r = e >> 6, c = e & 63;
            long row = kbase + (long)(kt * 64 + r) * 2304 + c;
            Ks[r][c] = qkv[row];
            Vs[r][c] = qkv[row + 768];
        }
        __syncthreads();
#pragma unroll
        for (int jj = 0; jj < 2; jj++) {
            int j = jj * 32 + lane;
            int kpos = kt * 64 + j;
            float mod = 0.0f;
            if (kpos <= qpos) {
                float s = 0.0f;
#pragma unroll
                for (int d = 0; d < 64; d++) s += qs[w][d] * Ks[j][d];
                s *= scale;
                float p = __expf(s - mval) * inv_z;
                float fire = 1.0f / (1.0f + __expf(-st * (p - th)));
                float wg = fire + lk * (1.0f - fire);
                mod = p * wg;
            }
            modbuf[w][j] = mod;
            smod += mod;
        }
        __syncwarp();
#pragma unroll 8
        for (int j = 0; j < 64; j++) {
            float mv = modbuf[w][j];
            acc0 += mv * Vs[j][d0];
            acc1 += mv * Vs[j][d1];
        }
    }
#pragma unroll
    for (int off = 16; off >= 1; off >>= 1)
        smod += __shfl_xor_sync(0xffffffffu, smod, off);
    float inv_s = 1.0f / (smod + 1e-8f);
    long yo = ((long)(b * Tt + qpos)) * Cc + hh * 64;
    y[yo + d0] = acc0 * inv_s;
    y[yo + d1] = acc1 * inv_s;
}

// ---------------- tied lm head ----------------
__global__ __launch_bounds__(256) void lmhead_kernel(const float* __restrict__ wte,
                                                     float* __restrict__ out) {
    __shared__ float xs[Bb * Cc];
    int tid = threadIdx.x;
    for (int i = tid; i < Bb * Cc; i += 256) xs[i] = g_xl[i];
    __syncthreads();
    int warp = tid >> 5, lane = tid & 31;
    int n = blockIdx.x * 8 + warp;
    if (n >= Vv) return;
    float acc[Bb];
#pragma unroll
    for (int r = 0; r < Bb; r++) acc[r] = 0.0f;
    const float* wrow = wte + (long)n * Cc;
    for (int k = lane; k < Cc; k += 32) {
        float wv = wrow[k];
#pragma unroll
        for (int r = 0; r < Bb; r++) acc[r] += wv * xs[r * Cc + k];
    }
#pragma unroll
    for (int r = 0; r < Bb; r++)
#pragma unroll
        for (int off = 16; off >= 1; off >>= 1)
            acc[r] += __shfl_xor_sync(0xffffffffu, acc[r], off);
    if (lane == 0) {
#pragma unroll
        for (int r = 0; r < Bb; r++) out[(long)r * Vv + n] = acc[r];
    }
}

extern "C" void kernel_launch(void* const* d_in, const int* in_sizes, int n_in,
                              void* d_out, int out_size) {
    const int* idx      = (const int*)d_in[0];
    const float* wte    = (const float*)d_in[1];
    const float* wpe    = (const float*)d_in[2];
    const float* ln1_w  = (const float*)d_in[3];
    const float* ln1_b  = (const float*)d_in[4];
    const float* attn_w = (const float*)d_in[5];
    const float* attn_b = (const float*)d_in[6];
    const float* proj_w = (const float*)d_in[7];
    const float* proj_b = (const float*)d_in[8];
    const float* thr    = (const float*)d_in[9];
    const float* leak   = (const float*)d_in[10];
    const float* steep  = (const float*)d_in[11];
    const float* ln2_w  = (const float*)d_in[12];
    const float* ln2_b  = (const float*)d_in[13];
    const float* fc_w   = (const float*)d_in[14];
    const float* fc_b   = (const float*)d_in[15];
    const float* mproj_w= (const float*)d_in[16];
    const float* mproj_b= (const float*)d_in[17];
    const float* lnf_w  = (const float*)d_in[18];
    const float* lnf_b  = (const float*)d_in[19];
    float* out = (float*)d_out;

    float *px, *ph, *py, *pqkv, *pm, *pxl;
    cudaGetSymbolAddress((void**)&px, g_x);
    cudaGetSymbolAddress((void**)&ph, g_h);
    cudaGetSymbolAddress((void**)&py, g_y);
    cudaGetSymbolAddress((void**)&pqkv, g_qkv);
    cudaGetSymbolAddress((void**)&pm, g_m);
    cudaGetSymbolAddress((void**)&pxl, g_xl);

    cudaFuncSetAttribute(mm_kernel<false, false>,
                         cudaFuncAttributeMaxDynamicSharedMemorySize, GEMM_SMEM_BYTES);
    cudaFuncSetAttribute(mm_kernel<false, true>,
                         cudaFuncAttributeMaxDynamicSharedMemorySize, GEMM_SMEM_BYTES);
    cudaFuncSetAttribute(mm_kernel<true, false>,
                         cudaFuncAttributeMaxDynamicSharedMemorySize, GEMM_SMEM_BYTES);

    const int Mrows = Bb * Tt;  // 8192

    embed_kernel<<<(Bb * Tt * Cc + 255) / 256, 256>>>(idx, wte, wpe);

    for (int l = 0; l < Ll; l++) {
        // ln1
        ln_kernel<<<Mrows, 256>>>(px, ph, ln1_w + l * Cc, ln1_b + l * Cc, Cc, 0);
        // qkv = h @ attn_w^T + attn_b
        {
            dim3 grid(3 * Cc / 128, Mrows / 128);
            mm_kernel<false, false><<<grid, 256, GEMM_SMEM_BYTES>>>(
                ph, attn_w + (long)l * 3 * Cc * Cc, attn_b + l * 3 * Cc,
                pqkv, pqkv, Mrows, 3 * Cc, Cc);
        }
        // attention
        {
            dim3 grid(Tt / 16, Hh, Bb);
            attn_kernel<<<grid, 512>>>(pqkv, py, thr + l * Hh, leak + l * Hh,
                                       steep + l * Hh);
        }
        // x = x + y @ proj_w^T + proj_b
        {
            dim3 grid(Cc / 128, Mrows / 128);
            mm_kernel<false, true><<<grid, 256, GEMM_SMEM_BYTES>>>(
                py, proj_w + (long)l * Cc * Cc, proj_b + l * Cc, px, px,
                Mrows, Cc, Cc);
        }
        // ln2
        ln_kernel<<<Mrows, 256>>>(px, ph, ln2_w + l * Cc, ln2_b + l * Cc, Cc, 0);
        // m = gelu(h @ fc_w^T + fc_b)
        {
            dim3 grid(4 * Cc / 128, Mrows / 128);
            mm_kernel<true, false><<<grid, 256, GEMM_SMEM_BYTES>>>(
                ph, fc_w + (long)l * 4 * Cc * Cc, fc_b + l * 4 * Cc, pm,
                pm, Mrows, 4 * Cc, Cc);
        }
        // x = x + m @ mproj_w^T + mproj_b
        {
            dim3 grid(Cc / 128, Mrows / 128);
            mm_kernel<false, true><<<grid, 256, GEMM_SMEM_BYTES>>>(
                pm, mproj_w + (long)l * Cc * 4 * Cc, mproj_b + l * Cc, px, px,
                Mrows, Cc, 4 * Cc);
        }
    }

    // lnf on last position of each batch row
    ln_kernel<<<Bb, 256>>>(px, pxl, lnf_w, lnf_b, (long)Tt * Cc,
                           (long)(Tt - 1) * Cc);
    // logits = xl @ wte^T
    lmhead_kernel<<<(Vv + 7) / 8, 256>>>(wte, out);
}